// round 1
// baseline (speedup 1.0000x reference)
#include <cuda_runtime.h>
#include <cstdint>

// Problem constants
#define BATCH 64
#define SEQ   1024
#define IDIM  256
#define HDIM  512
#define ODIM  128
#define G4    (4*HDIM)   // 2048

// ---------------- device scratch (static allocation only) ----------------
__device__ float g_xp[(size_t)SEQ * BATCH * G4];   // 512 MiB: forward input projection [t][b][4H]
__device__ float g_h[2][BATCH * HDIM];             // double-buffered hidden state [b][k]
__device__ float g_last[BATCH * 2 * HDIM];         // concat(h_fwd_last, h_bwd_last)
__device__ unsigned long long g_bar;               // monotonic grid-barrier counter

// ---------------- helpers ----------------
typedef unsigned long long ull;

__device__ __forceinline__ void ffma2(ull &acc, ull a, ull b) {
    asm("fma.rn.f32x2 %0, %1, %2, %0;" : "+l"(acc) : "l"(a), "l"(b));
}
__device__ __forceinline__ float2 unpack2(ull v) {
    float2 f;
    asm("mov.b64 {%0, %1}, %2;" : "=f"(f.x), "=f"(f.y) : "l"(v));
    return f;
}
__device__ __forceinline__ ull dup2(float a) {
    ull r;
    asm("mov.b64 %0, {%1, %1};" : "=l"(r) : "f"(a));
    return r;
}
__device__ __forceinline__ float sigf(float v) { return 1.0f / (1.0f + expf(-v)); }

// ================================================================
// Kernel 1: xp_f = relu(x) @ W_ih_f^T + b_f   (M=65536, N=2048, K=256)
// Tile 64x64x32, 256 threads, 4x4 microtile, f32x2 packed FMA.
// Row m of output = (t = blockIdx.y, b = row), i.e. m = t*64 + b.
// ================================================================
__global__ void __launch_bounds__(256) gemm_xp_kernel(
    const float* __restrict__ x, const float* __restrict__ Wih,
    const float* __restrict__ bias)
{
    __shared__ float As[32][68];  // [k][m]
    __shared__ float Bs[32][68];  // [k][n]

    const int t_idx = blockIdx.y;          // time index (M-tile)
    const int n0    = blockIdx.x * 64;     // N-tile
    const int tid   = threadIdx.x;
    const int tx    = tid & 15;            // col group
    const int ty    = tid >> 4;            // row group

    ull acc[4][2];
#pragma unroll
    for (int i = 0; i < 4; i++) { acc[i][0] = 0ull; acc[i][1] = 0ull; }

    for (int k0 = 0; k0 < IDIM; k0 += 32) {
        // load A tile: rows = batch b (0..63), cols = k0..k0+31, with relu
#pragma unroll
        for (int u = tid; u < 512; u += 256) {
            int row = u >> 3;             // b
            int kk  = (u & 7) << 2;
            float4 v = *(const float4*)(x + ((size_t)row * SEQ + t_idx) * IDIM + k0 + kk);
            As[kk + 0][row] = fmaxf(v.x, 0.f);
            As[kk + 1][row] = fmaxf(v.y, 0.f);
            As[kk + 2][row] = fmaxf(v.z, 0.f);
            As[kk + 3][row] = fmaxf(v.w, 0.f);
        }
        // load B tile: rows = gate col n, cols = k
#pragma unroll
        for (int u = tid; u < 512; u += 256) {
            int row = u >> 3;             // n - n0
            int kk  = (u & 7) << 2;
            float4 v = *(const float4*)(Wih + (size_t)(n0 + row) * IDIM + k0 + kk);
            Bs[kk + 0][row] = v.x;
            Bs[kk + 1][row] = v.y;
            Bs[kk + 2][row] = v.z;
            Bs[kk + 3][row] = v.w;
        }
        __syncthreads();

#pragma unroll 8
        for (int k = 0; k < 32; k++) {
            float4 a4 = *(const float4*)&As[k][ty << 2];
            ulonglong2 b2 = *(const ulonglong2*)&Bs[k][tx << 2];
            ull ad;
            ad = dup2(a4.x); ffma2(acc[0][0], ad, b2.x); ffma2(acc[0][1], ad, b2.y);
            ad = dup2(a4.y); ffma2(acc[1][0], ad, b2.x); ffma2(acc[1][1], ad, b2.y);
            ad = dup2(a4.z); ffma2(acc[2][0], ad, b2.x); ffma2(acc[2][1], ad, b2.y);
            ad = dup2(a4.w); ffma2(acc[3][0], ad, b2.x); ffma2(acc[3][1], ad, b2.y);
        }
        __syncthreads();
    }

    // epilogue: add bias, store to g_xp
    const int ncol = n0 + (tx << 2);
    float4 bv = *(const float4*)(bias + ncol);
#pragma unroll
    for (int i = 0; i < 4; i++) {
        int m = t_idx * 64 + (ty << 2) + i;   // = t*64 + b
        float2 p0 = unpack2(acc[i][0]);
        float2 p1 = unpack2(acc[i][1]);
        float4 o;
        o.x = p0.x + bv.x; o.y = p0.y + bv.y;
        o.z = p1.x + bv.z; o.w = p1.y + bv.w;
        *(float4*)(g_xp + (size_t)m * G4 + ncol) = o;
    }
}

// ================================================================
// Kernel 2: backward-direction last hidden state (single LSTM step from 0).
// h_b[S-1] = sigmoid(o) * tanh( sigmoid(i) * tanh(g) ),  gates from
// relu(x[:,S-1,:]) @ W_ih_b^T + b_b.  f gate unused (c0 = 0).
// ================================================================
__global__ void __launch_bounds__(256) bwd_last_kernel(
    const float* __restrict__ x, const float* __restrict__ Wb,
    const float* __restrict__ bb)
{
    __shared__ float xr[IDIM];
    const int b = blockIdx.x, tid = threadIdx.x;
    xr[tid] = fmaxf(x[((size_t)b * SEQ + (SEQ - 1)) * IDIM + tid], 0.f);
    __syncthreads();

    for (int j = tid; j < HDIM; j += 256) {
        const int cols[3] = { j, 2 * HDIM + j, 3 * HDIM + j };   // i, g, o
        float acc[3] = { bb[cols[0]], bb[cols[1]], bb[cols[2]] };
#pragma unroll
        for (int gi = 0; gi < 3; gi++) {
            const float4* wp = (const float4*)(Wb + (size_t)cols[gi] * IDIM);
            float s = 0.f;
#pragma unroll 8
            for (int k4 = 0; k4 < IDIM / 4; k4++) {
                float4 w = __ldg(wp + k4);
                float4 xv = *(const float4*)&xr[k4 * 4];
                s += w.x * xv.x + w.y * xv.y + w.z * xv.z + w.w * xv.w;
            }
            acc[gi] += s;
        }
        float cst = sigf(acc[0]) * tanhf(acc[1]);
        float h   = sigf(acc[2]) * tanhf(cst);
        g_last[b * (2 * HDIM) + HDIM + j] = h;
    }
}

// ================================================================
// Kernel 3: persistent forward LSTM scan. 128 blocks x 256 threads,
// one block per SM, all co-resident. Each block owns 4 H-columns
// (16 gate columns). W_hh slice held in SMEM for all 1024 steps.
// h exchanged through double-buffered global memory (L2), one grid
// barrier per step (monotonic counter -> graph-replay safe).
// ================================================================
#define SCAN_BLOCKS 128
#define WPAD 516                       // 512 + 4 pad floats
#define SCAN_SMEM ((16*WPAD + 64*WPAD + 64*16) * 4)

__device__ __forceinline__ void gridbar() {
    __syncthreads();
    if (threadIdx.x == 0) {
        __threadfence();
        ull old = atomicAdd(&g_bar, 1ull);
        ull target = (old / SCAN_BLOCKS + 1) * SCAN_BLOCKS;
        ull v;
        do {
            asm volatile("ld.acquire.gpu.global.u64 %0, [%1];"
                         : "=l"(v) : "l"(&g_bar) : "memory");
        } while (v < target);
    }
    __syncthreads();
}

__global__ void __launch_bounds__(256, 1) lstm_scan_kernel(const float* __restrict__ Whh)
{
    extern __shared__ float sm[];
    float* ws = sm;                    // [16][WPAD]  W_hh slice, [col][k]
    float* hs = sm + 16 * WPAD;        // [64][WPAD]  h, [b][k]
    float* gs = hs + 64 * WPAD;        // [64][16]    gates

    const int tid = threadIdx.x;
    const int j0  = blockIdx.x * 4;    // this block's 4 H-columns

    // one-time load of W_hh slice (16 gate columns x 512)
    for (int u = tid; u < 16 * HDIM; u += 256) {
        int cc = u >> 9;               // local col 0..15
        int k  = u & (HDIM - 1);
        int gate = cc >> 2, jl = cc & 3;
        ws[cc * WPAD + k] = Whh[(size_t)(gate * HDIM + j0 + jl) * HDIM + k];
    }

    // gate-compute role
    const int c    = tid & 15;         // local gate col
    const int bg   = tid >> 4;         // batch group (4 rows)
    const int gate = c >> 2, jl = c & 3;
    const int colg = gate * HDIM + j0 + jl;
    const float* wrow = ws + c * WPAD;
    const float* h0p = hs + (bg * 4 + 0) * WPAD;
    const float* h1p = hs + (bg * 4 + 1) * WPAD;
    const float* h2p = hs + (bg * 4 + 2) * WPAD;
    const float* h3p = hs + (bg * 4 + 3) * WPAD;

    // update role
    const int ub  = tid >> 2;
    const int ujl = tid & 3;
    float cstate = 0.f;

    __syncthreads();

    for (int t = 0; t < SEQ; t++) {
        // ---- stage h_prev into SMEM ----
        if (t == 0) {
            for (int u = tid; u < (64 * WPAD) / 4; u += 256)
                *(float4*)(hs + u * 4) = make_float4(0.f, 0.f, 0.f, 0.f);
        } else {
            const float4* src = (const float4*)g_h[t & 1];
#pragma unroll 8
            for (int u = tid; u < (BATCH * HDIM) / 4; u += 256) {
                float4 v = __ldcg(src + u);
                int b  = u >> 7;                 // 128 float4 per row
                int kk = (u & 127) << 2;
                *(float4*)(hs + b * WPAD + kk) = v;
            }
        }
        __syncthreads();

        // ---- gate dot products: 4 batches x 1 gate col, f32x2 packed ----
        ull a0 = 0, a1 = 0, a2 = 0, a3 = 0;
        ull b0 = 0, b1 = 0, b2 = 0, b3 = 0;
#pragma unroll 4
        for (int k = 0; k < HDIM; k += 4) {
            ulonglong2 w2 = *(const ulonglong2*)(wrow + k);
            ulonglong2 q;
            q = *(const ulonglong2*)(h0p + k); ffma2(a0, q.x, w2.x); ffma2(b0, q.y, w2.y);
            q = *(const ulonglong2*)(h1p + k); ffma2(a1, q.x, w2.x); ffma2(b1, q.y, w2.y);
            q = *(const ulonglong2*)(h2p + k); ffma2(a2, q.x, w2.x); ffma2(b2, q.y, w2.y);
            q = *(const ulonglong2*)(h3p + k); ffma2(a3, q.x, w2.x); ffma2(b3, q.y, w2.y);
        }
        {
            const float* xprow = g_xp + (size_t)t * BATCH * G4;
            float2 pa, pb;
            int bb0 = bg * 4;
            pa = unpack2(a0); pb = unpack2(b0);
            gs[(bb0 + 0) * 16 + c] = (pa.x + pa.y) + (pb.x + pb.y) + __ldcs(xprow + (size_t)(bb0 + 0) * G4 + colg);
            pa = unpack2(a1); pb = unpack2(b1);
            gs[(bb0 + 1) * 16 + c] = (pa.x + pa.y) + (pb.x + pb.y) + __ldcs(xprow + (size_t)(bb0 + 1) * G4 + colg);
            pa = unpack2(a2); pb = unpack2(b2);
            gs[(bb0 + 2) * 16 + c] = (pa.x + pa.y) + (pb.x + pb.y) + __ldcs(xprow + (size_t)(bb0 + 2) * G4 + colg);
            pa = unpack2(a3); pb = unpack2(b3);
            gs[(bb0 + 3) * 16 + c] = (pa.x + pa.y) + (pb.x + pb.y) + __ldcs(xprow + (size_t)(bb0 + 3) * G4 + colg);
        }
        __syncthreads();

        // ---- cell update: thread owns (b=ub, j=j0+ujl), c-state in register ----
        {
            float gi = gs[ub * 16 + 0 + ujl];
            float gf = gs[ub * 16 + 4 + ujl];
            float gg = gs[ub * 16 + 8 + ujl];
            float go = gs[ub * 16 + 12 + ujl];
            float i_ = sigf(gi), f_ = sigf(gf);
            float g_ = tanhf(gg), o_ = sigf(go);
            cstate = fmaf(f_, cstate, i_ * g_);
            float h = o_ * tanhf(cstate);
            __stcg(&g_h[(t + 1) & 1][ub * HDIM + j0 + ujl], h);
            if (t == SEQ - 1)
                g_last[ub * (2 * HDIM) + j0 + ujl] = h;
        }

        if (t < SEQ - 1) gridbar();
    }
}

// ================================================================
// Kernel 4: final FC  out[b][o] = last[b] . W_fc[o] + b_fc[o]
// ================================================================
__global__ void __launch_bounds__(128) fc_kernel(
    const float* __restrict__ Wfc, const float* __restrict__ bfc,
    float* __restrict__ out)
{
    __shared__ float ls[2 * HDIM];
    const int b = blockIdx.x, o = threadIdx.x;
    for (int u = o; u < 2 * HDIM; u += 128) ls[u] = g_last[b * (2 * HDIM) + u];
    __syncthreads();

    float acc = bfc[o];
    const float4* wp = (const float4*)(Wfc + (size_t)o * (2 * HDIM));
#pragma unroll 8
    for (int k4 = 0; k4 < (2 * HDIM) / 4; k4++) {
        float4 w = __ldg(wp + k4);
        float4 l = *(const float4*)&ls[k4 * 4];
        acc += w.x * l.x + w.y * l.y + w.z * l.z + w.w * l.w;
    }
    out[b * ODIM + o] = acc;
}

// ================================================================
extern "C" void kernel_launch(void* const* d_in, const int* in_sizes, int n_in,
                              void* d_out, int out_size)
{
    const float* x      = (const float*)d_in[0];
    const float* W_ih_f = (const float*)d_in[1];
    const float* W_hh_f = (const float*)d_in[2];
    const float* b_f    = (const float*)d_in[3];
    const float* W_ih_b = (const float*)d_in[4];
    // const float* W_hh_b = (const float*)d_in[5];   // unused: bwd last state needs no recurrence
    const float* b_b    = (const float*)d_in[6];
    const float* W_fc   = (const float*)d_in[7];
    const float* b_fc   = (const float*)d_in[8];
    float* out = (float*)d_out;

    cudaFuncSetAttribute(lstm_scan_kernel,
                         cudaFuncAttributeMaxDynamicSharedMemorySize, SCAN_SMEM);

    gemm_xp_kernel<<<dim3(G4 / 64, SEQ), 256>>>(x, W_ih_f, b_f);
    bwd_last_kernel<<<BATCH, 256>>>(x, W_ih_b, b_b);
    lstm_scan_kernel<<<SCAN_BLOCKS, 256, SCAN_SMEM>>>(W_hh_f);
    fc_kernel<<<BATCH, 128>>>(W_fc, b_fc, out);
}